// round 9
// baseline (speedup 1.0000x reference)
#include <cuda_runtime.h>
#include <math_constants.h>

#define BB   32
#define NPF  100
#define FIN  36
#define KNN  11
#define FC   40
#define HH   3600
#define NLL  5
#define EPS_BN 1e-3f
#define NB   225          // grid blocks (225*16 = 3600 cols)
#define NT   256          // threads per block

// ---------------- scratch (static, allocation-free) ----------------
__device__ float d_x[BB * NPF * FC];        // preprocessed features
__device__ float d_g[BB * KNN * FC];        // gathered knn features (B x 440)
__device__ float d_hA[BB * HH];
__device__ float d_hB[BB * HH];
__device__ float d_r[NLL * HH];             // rsqrtf(mvar + eps), matching lax.rsqrt lowering

__device__ unsigned bar_cnt = 0;
__device__ unsigned bar_gen = 0;

// grid-wide barrier: all NB blocks are co-resident by construction (NB=225 <= 2*148).
__device__ __forceinline__ void grid_bar()
{
    __syncthreads();
    if (threadIdx.x == 0) {
        __threadfence();
        unsigned gen = *((volatile unsigned*)&bar_gen);
        if (atomicAdd(&bar_cnt, 1u) == NB - 1) {
            bar_cnt = 0;
            __threadfence();
            *((volatile unsigned*)&bar_gen) = gen + 1;
        } else {
            while (*((volatile unsigned*)&bar_gen) == gen) __nanosleep(64);
        }
        __threadfence();
    }
    __syncthreads();
}

#define FMA16(ACC, XV, WPTR) do {                                   \
    const float4* _w4 = (const float4*)(WPTR);                      \
    float4 _w0 = _w4[0], _w1 = _w4[1], _w2 = _w4[2], _w3 = _w4[3];  \
    ACC[0]  += (XV) * _w0.x; ACC[1]  += (XV) * _w0.y;               \
    ACC[2]  += (XV) * _w0.z; ACC[3]  += (XV) * _w0.w;               \
    ACC[4]  += (XV) * _w1.x; ACC[5]  += (XV) * _w1.y;               \
    ACC[6]  += (XV) * _w1.z; ACC[7]  += (XV) * _w1.w;               \
    ACC[8]  += (XV) * _w2.x; ACC[9]  += (XV) * _w2.y;               \
    ACC[10] += (XV) * _w2.z; ACC[11] += (XV) * _w2.w;               \
    ACC[12] += (XV) * _w3.x; ACC[13] += (XV) * _w3.y;               \
    ACC[14] += (XV) * _w3.z; ACC[15] += (XV) * _w3.w;               \
} while (0)

// GEMM layer: 32 x KD  @  KD x 3600, block owns 16 cols, 8 warps split K.
// Epilogue applies UNFOLDED batchnorm exactly in the reference op order:
//   relu( gamma*(((s + bias) - mmean)) * r + beta ),  r = rsqrtf(mvar+eps)
__device__ __forceinline__ void gemm_layer(const float* __restrict__ in,
                                           const float* __restrict__ W,
                                           float* __restrict__ out,
                                           int KD, int kt, int layer,
                                           const float* __restrict__ bias,
                                           const float* __restrict__ gamma,
                                           const float* __restrict__ beta,
                                           const float* __restrict__ mmean,
                                           float* s_x, float* s_red)
{
    const int col0 = blockIdx.x * 16;
    const int tid  = threadIdx.x;
    const int w    = tid >> 5;
    const int lane = tid & 31;
    const int sub  = kt >> 3;
    const int strd = kt + 1;      // padded (73 or 41) -> conflict-free

    float accA[16], accB[16];
#pragma unroll
    for (int c = 0; c < 16; c++) { accA[c] = 0.f; accB[c] = 0.f; }

    for (int k0 = 0; k0 < KD; k0 += kt) {
        // cooperative stage of x[32][kt] into smem
        const int nseg = kt >> 2;
        for (int i = tid; i < 32 * nseg; i += NT) {
            int row = i / nseg, seg = i % nseg;
            float4 v = *(const float4*)(in + (size_t)row * KD + k0 + seg * 4);
            float* dst = s_x + row * strd + seg * 4;
            dst[0] = v.x; dst[1] = v.y; dst[2] = v.z; dst[3] = v.w;
        }
        __syncthreads();

        const float* xrow = s_x + lane * strd + w * sub;
        const float* Wp   = W + (size_t)(k0 + w * sub) * HH + col0;
        int kk = 0;
        for (; kk + 1 < sub; kk += 2) {
            float xv0 = xrow[kk];
            FMA16(accA, xv0, Wp); Wp += HH;
            float xv1 = xrow[kk + 1];
            FMA16(accB, xv1, Wp); Wp += HH;
        }
        if (kk < sub) {
            float xv0 = xrow[kk];
            FMA16(accA, xv0, Wp);
        }
        __syncthreads();
    }

    // per-warp partial, cross-warp reduce in double, then unfolded BN + ReLU
#pragma unroll
    for (int c = 0; c < 16; c++) s_red[w * 512 + lane * 16 + c] = accA[c] + accB[c];
    __syncthreads();
    for (int o = tid; o < 512; o += NT) {
        double s = 0.0;
#pragma unroll
        for (int ww = 0; ww < 8; ww++) s += (double)s_red[ww * 512 + o];
        int row = o >> 4, c = o & 15;
        int col = col0 + c;
        float sf = (float)s;
        // reference op order: h = dot + bias; u = h - mmean; v = ((gamma*u)*r) + beta
        float h1 = __fadd_rn(sf, bias[col]);
        float u  = __fsub_rn(h1, mmean[col]);
        float v  = __fadd_rn(__fmul_rn(__fmul_rn(gamma[col], u),
                                       d_r[layer * HH + col]),
                             beta[col]);
        out[(size_t)row * HH + col] = fmaxf(v, 0.f);
    }
}

__global__ void __launch_bounds__(NT, 2)
mega_kernel(const float* __restrict__ xx,
            const float* __restrict__ e1, const float* __restrict__ e2,
            const float* __restrict__ e3,
            const float* __restrict__ mean, const float* __restrict__ stdv,
            const float* __restrict__ vmin, const float* __restrict__ vmax,
            const float* __restrict__ W0,  const float* __restrict__ b0,
            const float* __restrict__ Wh,  const float* __restrict__ bh,
            const float* __restrict__ gamma, const float* __restrict__ beta,
            const float* __restrict__ mmean, const float* __restrict__ mvar,
            const float* __restrict__ Wc,  const float* __restrict__ bc,
            const float* __restrict__ W2,  const float* __restrict__ b2,
            const float* __restrict__ W100,const float* __restrict__ b100,
            float* __restrict__ out)
{
    __shared__ float s_x[32 * 73];     // x stage / sel+final scratch
    __shared__ float s_red[4096];      // warp-partial reduce / block reduce
    __shared__ int   s_idx[KNN];

    const int bid = blockIdx.x;
    const int tid = threadIdx.x;
    const int gtid = bid * NT + tid;

    // -------- preprocessing (contraction-free IEEE ops) --------
    for (int idx = gtid; idx < BB * NPF; idx += NB * NT) {
        const float* r = xx + (size_t)idx * FIN;
        float* o = d_x + (size_t)idx * FC;
        int i1 = (int)fabsf(r[0]);
        int i2 = (int)fabsf(r[1]);
        int i3 = (int)fabsf(r[2]);
        o[0] = e1[i1 * 2]; o[1] = e1[i1 * 2 + 1];
        o[2] = e2[i2 * 2]; o[3] = e2[i2 * 2 + 1];
        o[4] = e3[i3 * 2]; o[5] = e3[i3 * 2 + 1];
#pragma unroll
        for (int f = 2; f < FIN; f++) {
            float v = r[f];
            if (f >= 3) {
                float y = __fdiv_rn(__fsub_rn(v, mean[f]), stdv[f]);
                y = fminf(fmaxf(y, -5.f), 5.f);
                float sc = __fdiv_rn(2.f, __fsub_rn(vmax[f], vmin[f]));
                y = __fsub_rn(__fmul_rn(sc, __fsub_rn(y, vmin[f])), 1.f);
                y = fminf(fmaxf(y, -1.f), 1.f);
                v = y;
            }
            o[6 + f - 2] = v;
        }
    }
    // -------- per-channel rsqrt (matches lax.rsqrt -> __nv_rsqrtf on GPU) --------
    for (int idx = gtid; idx < NLL * HH; idx += NB * NT) {
        d_r[idx] = rsqrtf(__fadd_rn(mvar[idx], EPS_BN));
    }
    grid_bar();

    // -------- 100 sequential knn+MLP steps --------
    for (int it = 0; it < NPF; it++) {
        // ---- selection (blocks 0..31, one per batch element) ----
        if (bid < BB) {
            const int b = bid;
            const float* xb = d_x + (size_t)b * NPF * FC;
            float r0, r1;
            if (it == 0) {
                r0 = xb[12];  // ETA_C of particle 0
                r1 = xb[13];  // PHI_C
            } else {
                const float* hb = d_hA + (size_t)b * HH;
                double a0 = 0.0, a1 = 0.0;
                for (int k = tid; k < HH; k += NT) {
                    double hv = (double)hb[k];
                    a0 += hv * (double)Wc[2 * k];
                    a1 += hv * (double)Wc[2 * k + 1];
                }
                double* dred = (double*)s_red;     // 2048 doubles capacity
                dred[tid] = a0; dred[NT + tid] = a1;
                __syncthreads();
                for (int s = NT / 2; s > 0; s >>= 1) {
                    if (tid < s) {
                        dred[tid]      += dred[tid + s];
                        dred[NT + tid] += dred[NT + tid + s];
                    }
                    __syncthreads();
                }
                r0 = __fadd_rn((float)dred[0],  bc[0]);
                r1 = __fadd_rn((float)dred[NT], bc[1]);
                __syncthreads();
            }
            if (tid < NPF) {
                float de = __fsub_rn(xb[tid * FC + 12], r0);
                float dp = __fsub_rn(xb[tid * FC + 13], r1);
                s_x[tid] = sqrtf(__fadd_rn(__fmul_rn(de, de), __fmul_rn(dp, dp)));
            }
            __syncthreads();
            if (tid == 0) {
                // stable top-11: smallest distance, ties -> smallest index
                for (int s = 0; s < KNN; s++) {
                    float best = CUDART_INF_F; int bi = 0;
                    for (int p = 0; p < NPF; p++) {
                        float v = s_x[p];
                        if (v < best) { best = v; bi = p; }
                    }
                    s_idx[s] = bi;
                    s_x[bi] = CUDART_INF_F;
                }
            }
            __syncthreads();
            for (int i = tid; i < KNN * FC; i += NT) {
                int s = i / FC, f = i % FC;
                int bi = s_idx[s];
                d_g[(size_t)b * (KNN * FC) + i] = xb[bi * FC + f];
            }
        }
        grid_bar();

        // ---- MLP: layer 0 (K=440), layers 1..4 (K=3600) ----
        gemm_layer(d_g, W0, d_hA, KNN * FC, 40, 0,
                   b0, gamma, beta, mmean, s_x, s_red);
        grid_bar();
        gemm_layer(d_hA, Wh,                   d_hB, HH, 72, 1,
                   bh,            gamma + HH,   beta + HH,   mmean + HH,   s_x, s_red); grid_bar();
        gemm_layer(d_hB, Wh + (size_t)1*HH*HH, d_hA, HH, 72, 2,
                   bh + HH,       gamma + 2*HH, beta + 2*HH, mmean + 2*HH, s_x, s_red); grid_bar();
        gemm_layer(d_hA, Wh + (size_t)2*HH*HH, d_hB, HH, 72, 3,
                   bh + 2*HH,     gamma + 3*HH, beta + 3*HH, mmean + 3*HH, s_x, s_red); grid_bar();
        gemm_layer(d_hB, Wh + (size_t)3*HH*HH, d_hA, HH, 72, 4,
                   bh + 3*HH,     gamma + 4*HH, beta + 4*HH, mmean + 4*HH, s_x, s_red); grid_bar();
    }

    // -------- final epilogue (blocks 0..31) --------
    if (bid < BB) {
        const int b = bid;
        const float* hb = d_hA + (size_t)b * HH;
        float* slog = s_x;            // 100 logits
        float* sred = s_red;          // 256 reduce
        int w = tid >> 5, lane = tid & 31;

        // logits h @ W100 + b100
        for (int p = w; p < NPF; p += 8) {
            float acc = 0.f;
            for (int k = lane; k < HH; k += 32)
                acc += hb[k] * W100[(size_t)k * NPF + p];
#pragma unroll
            for (int o = 16; o; o >>= 1) acc += __shfl_down_sync(0xffffffffu, acc, o);
            if (lane == 0) slog[p] = acc + b100[p];
        }
        // x2 dots
        float a0 = 0.f, a1 = 0.f;
        for (int k = tid; k < HH; k += NT) {
            float hv = hb[k];
            a0 += hv * W2[2 * k];
            a1 += hv * W2[2 * k + 1];
        }
        __syncthreads();
        sred[tid] = a0; __syncthreads();
        for (int s = 128; s > 0; s >>= 1) { if (tid < s) sred[tid] += sred[tid + s]; __syncthreads(); }
        float x20 = sred[0] + b2[0]; __syncthreads();
        sred[tid] = a1; __syncthreads();
        for (int s = 128; s > 0; s >>= 1) { if (tid < s) sred[tid] += sred[tid + s]; __syncthreads(); }
        float x21 = sred[0] + b2[1]; __syncthreads();

        // softmax
        float mx = -CUDART_INF_F;
        for (int p = tid; p < NPF; p += NT) mx = fmaxf(mx, slog[p]);
        sred[tid] = mx; __syncthreads();
        for (int s = 128; s > 0; s >>= 1) { if (tid < s) sred[tid] = fmaxf(sred[tid], sred[tid + s]); __syncthreads(); }
        mx = sred[0]; __syncthreads();
        float es = 0.f;
        for (int p = tid; p < NPF; p += NT) {
            float e = expf(slog[p] - mx);
            slog[p] = e;
            es += e;
        }
        sred[tid] = es; __syncthreads();
        for (int s = 128; s > 0; s >>= 1) { if (tid < s) sred[tid] += sred[tid + s]; __syncthreads(); }
        es = sred[0]; __syncthreads();

        // weighted physics sums
        float px = 0.f, py = 0.f, pz = 0.f, E = 0.f;
        for (int p = tid; p < NPF; p += NT) {
            const float* xr = xx + ((size_t)b * NPF + p) * FIN;
            float wv = (slog[p] / es) * xr[7];
            px += xr[3] * wv; py += xr[4] * wv;
            pz += xr[5] * wv; E  += xr[6] * wv;
        }
        sred[tid] = px; __syncthreads();
        for (int s = 128; s > 0; s >>= 1) { if (tid < s) sred[tid] += sred[tid + s]; __syncthreads(); }
        px = sred[0]; __syncthreads();
        sred[tid] = py; __syncthreads();
        for (int s = 128; s > 0; s >>= 1) { if (tid < s) sred[tid] += sred[tid + s]; __syncthreads(); }
        py = sred[0]; __syncthreads();
        sred[tid] = pz; __syncthreads();
        for (int s = 128; s > 0; s >>= 1) { if (tid < s) sred[tid] += sred[tid + s]; __syncthreads(); }
        pz = sred[0]; __syncthreads();
        sred[tid] = E; __syncthreads();
        for (int s = 128; s > 0; s >>= 1) { if (tid < s) sred[tid] += sred[tid + s]; __syncthreads(); }
        E = sred[0]; __syncthreads();

        if (tid == 0) {
            float px2 = px * px, py2 = py * py, pz2 = pz * pz;
            float pt = sqrtf(px2 + py2);
            float mass2 = E * E - px2 - py2 - pz2;
            float absp = sqrtf(px2 + py2 + pz2);
            float cosT = (absp == 0.f) ? 1.f : pz / absp;
            bool okc = cosT * cosT < 1.f;
            float ratio = okc ? (1.f - cosT) / (1.f + cosT) : 1.f;
            float eta = okc ? -0.5f * logf(ratio) : 0.f;
            float phi = (px == 0.f && py == 0.f) ? 0.f : atan2f(py, px);
            out[b * 6 + 0] = x20;
            out[b * 6 + 1] = x21;
            out[b * 6 + 2] = pt;
            out[b * 6 + 3] = eta;
            out[b * 6 + 4] = phi;
            out[b * 6 + 5] = mass2;
        }
    }
}

// ---------------- launcher: ONE node in the graph ----------------
extern "C" void kernel_launch(void* const* d_in, const int* in_sizes, int n_in,
                              void* d_out, int out_size)
{
    mega_kernel<<<NB, NT>>>(
        (const float*)d_in[0],  (const float*)d_in[1],  (const float*)d_in[2],
        (const float*)d_in[3],  (const float*)d_in[4],  (const float*)d_in[5],
        (const float*)d_in[6],  (const float*)d_in[7],  (const float*)d_in[8],
        (const float*)d_in[9],  (const float*)d_in[10], (const float*)d_in[11],
        (const float*)d_in[12], (const float*)d_in[13], (const float*)d_in[14],
        (const float*)d_in[15], (const float*)d_in[16], (const float*)d_in[17],
        (const float*)d_in[18], (const float*)d_in[19], (const float*)d_in[20],
        (const float*)d_in[21], (float*)d_out);
}

// round 10
// speedup vs baseline: 2.1798x; 2.1798x over previous
#include <cuda_runtime.h>
#include <math_constants.h>

#define BB   32
#define NPF  100
#define FIN  36
#define KNN  11
#define FC   40
#define HH   3600
#define NLL  5
#define EPS_BN 1e-3f
#define NB   225          // grid blocks (225*16 = 3600 cols)
#define NT   256          // threads per block

// ---------------- scratch (static, allocation-free) ----------------
__device__ float d_x[BB * NPF * FC];        // preprocessed features
__device__ float d_g[BB * KNN * FC];        // gathered knn features (B x 440)
__device__ float d_hA[BB * HH];
__device__ float d_hB[BB * HH];
__device__ float d_r[NLL * HH];             // rsqrtf(mvar + eps)

__device__ unsigned bar_cnt = 0;
__device__ unsigned bar_gen = 0;

// grid-wide barrier: all NB blocks are co-resident by construction (NB=225 <= 2*148).
__device__ __forceinline__ void grid_bar()
{
    __syncthreads();
    if (threadIdx.x == 0) {
        __threadfence();
        unsigned gen = *((volatile unsigned*)&bar_gen);
        if (atomicAdd(&bar_cnt, 1u) == NB - 1) {
            bar_cnt = 0;
            __threadfence();
            *((volatile unsigned*)&bar_gen) = gen + 1;
        } else {
            while (*((volatile unsigned*)&bar_gen) == gen) __nanosleep(64);
        }
        __threadfence();
    }
    __syncthreads();
}

// ---------------- cp.async helpers ----------------
__device__ __forceinline__ void cp16(unsigned d, const void* s)
{
    asm volatile("cp.async.ca.shared.global [%0], [%1], 16;" :: "r"(d), "l"(s));
}
__device__ __forceinline__ void cp4(unsigned d, const void* s)
{
    asm volatile("cp.async.ca.shared.global [%0], [%1], 4;" :: "r"(d), "l"(s));
}
#define CP_COMMIT() asm volatile("cp.async.commit_group;")
#define CP_WAIT(N)  asm volatile("cp.async.wait_group %0;" :: "n"(N))

// packed fp32x2 FMA: two independent IEEE-rn FMAs (identical to scalar sequence)
__device__ __forceinline__ void ffma2(unsigned long long& acc,
                                      unsigned long long x2,
                                      unsigned long long w2)
{
    asm("fma.rn.f32x2 %0, %1, %2, %0;" : "+l"(acc) : "l"(x2), "l"(w2));
}
__device__ __forceinline__ unsigned long long add2(unsigned long long a,
                                                   unsigned long long b)
{
    unsigned long long r;
    asm("add.rn.f32x2 %0, %1, %2;" : "=l"(r) : "l"(a), "l"(b));
    return r;
}

// GEMM layer: 32 x KD  @  KD x 3600, block owns 16 cols, 8 warps split K.
// Double-buffered cp.async staging (W tile + transposed x tile), FFMA2 inner loop.
// Numerically IDENTICAL to the scalar dual-bank version (same per-acc FMA order,
// same A/B bank alternation, same double cross-warp reduce, unfolded BN).
template <int KT, int NTILE>
__device__ __forceinline__ void gemm_layer(const float* __restrict__ in,
                                           const float* __restrict__ W,
                                           float* __restrict__ out,
                                           int KD, int layer,
                                           const float* __restrict__ bias,
                                           const float* __restrict__ gamma,
                                           const float* __restrict__ beta,
                                           const float* __restrict__ mmean,
                                           float* s_w, float* s_xt, float* s_red)
{
    constexpr int SUB = KT / 8;       // k-values per warp per tile
    const int col0 = blockIdx.x * 16;
    const int tid  = threadIdx.x;
    const int w    = tid >> 5;
    const int lane = tid & 31;

    const unsigned sw_base = (unsigned)__cvta_generic_to_shared(s_w);
    const unsigned sx_base = (unsigned)__cvta_generic_to_shared(s_xt);

    unsigned long long accA[8], accB[8];
#pragma unroll
    for (int j = 0; j < 8; j++) { accA[j] = 0ull; accB[j] = 0ull; }

    // ---- tile loader: W[KT][16] (16B copies) + x transposed [KT][m] (4B copies)
    auto load_tile = [&](int buf, int k0) {
#pragma unroll 2
        for (int i = tid; i < KT * 4; i += NT) {
            int row = i >> 2, seg = i & 3;
            cp16(sw_base + (unsigned)(buf * KT * 16 + row * 16 + seg * 4) * 4,
                 W + (size_t)(k0 + row) * HH + col0 + seg * 4);
        }
#pragma unroll
        for (int i = tid; i < KT * 32; i += NT) {
            int m = i / KT, k = i - m * KT;
            cp4(sx_base + (unsigned)(buf * KT * 37 + k * 37 + m) * 4,
                in + (size_t)m * KD + k0 + k);
        }
        CP_COMMIT();
    };

    load_tile(0, 0);

    int buf = 0;
#pragma unroll 1
    for (int t = 0; t < NTILE; t++) {
        if (t + 1 < NTILE) {
            load_tile(buf ^ 1, (t + 1) * KT);
            CP_WAIT(1);
        } else {
            CP_WAIT(0);
        }
        __syncthreads();

        const float* xk = s_xt + buf * KT * 37 + lane;
        const float* wk = s_w + buf * KT * 16;
        const int kbase = w * SUB;

#pragma unroll
        for (int kk = 0; kk < SUB; kk++) {
            const int k = kbase + kk;
            float xv = xk[k * 37];
            unsigned long long x2;
            asm("mov.b64 %0, {%1, %1};" : "=l"(x2) : "f"(xv));
            const ulonglong2* wp = (const ulonglong2*)(wk + k * 16);
            ulonglong2 q0 = wp[0], q1 = wp[1], q2 = wp[2], q3 = wp[3];
            unsigned long long* acc = (kk & 1) ? accB : accA;
            ffma2(acc[0], x2, q0.x); ffma2(acc[1], x2, q0.y);
            ffma2(acc[2], x2, q1.x); ffma2(acc[3], x2, q1.y);
            ffma2(acc[4], x2, q2.x); ffma2(acc[5], x2, q2.y);
            ffma2(acc[6], x2, q3.x); ffma2(acc[7], x2, q3.y);
        }
        __syncthreads();
        buf ^= 1;
    }

    // per-warp partial = A + B (packed add = identical scalar adds)
#pragma unroll
    for (int j = 0; j < 8; j++) {
        unsigned long long s2 = add2(accA[j], accB[j]);
        unsigned lo, hi;
        asm("mov.b64 {%0, %1}, %2;" : "=r"(lo), "=r"(hi) : "l"(s2));
        s_red[w * 512 + lane * 16 + 2 * j]     = __uint_as_float(lo);
        s_red[w * 512 + lane * 16 + 2 * j + 1] = __uint_as_float(hi);
    }
    __syncthreads();
    for (int o = tid; o < 512; o += NT) {
        double s = 0.0;
#pragma unroll
        for (int ww = 0; ww < 8; ww++) s += (double)s_red[ww * 512 + o];
        int row = o >> 4, c = o & 15;
        int col = col0 + c;
        float sf = (float)s;
        // reference op order: h = dot + bias; u = h - mmean; v = ((gamma*u)*r) + beta
        float h1 = __fadd_rn(sf, bias[col]);
        float u  = __fsub_rn(h1, mmean[col]);
        float v  = __fadd_rn(__fmul_rn(__fmul_rn(gamma[col], u),
                                       d_r[layer * HH + col]),
                             beta[col]);
        out[(size_t)row * HH + col] = fmaxf(v, 0.f);
    }
    __syncthreads();
}

__global__ void __launch_bounds__(NT, 2)
mega_kernel(const float* __restrict__ xx,
            const float* __restrict__ e1, const float* __restrict__ e2,
            const float* __restrict__ e3,
            const float* __restrict__ mean, const float* __restrict__ stdv,
            const float* __restrict__ vmin, const float* __restrict__ vmax,
            const float* __restrict__ W0,  const float* __restrict__ b0,
            const float* __restrict__ Wh,  const float* __restrict__ bh,
            const float* __restrict__ gamma, const float* __restrict__ beta,
            const float* __restrict__ mmean, const float* __restrict__ mvar,
            const float* __restrict__ Wc,  const float* __restrict__ bc,
            const float* __restrict__ W2,  const float* __restrict__ b2,
            const float* __restrict__ W100,const float* __restrict__ b100,
            float* __restrict__ out)
{
    __shared__ __align__(16) float s_w[2 * 72 * 16];     // W tiles (double buffer)
    __shared__ __align__(16) float s_xt[2 * 72 * 37];    // x tiles, transposed [k][m]
    __shared__ float s_red[4096];                        // reduces (also as double[2048])
    __shared__ float s_sel[128];                         // distances / logits scratch
    __shared__ int   s_idx[KNN];

    const int bid = blockIdx.x;
    const int tid = threadIdx.x;
    const int gtid = bid * NT + tid;

    // -------- preprocessing (contraction-free IEEE ops) --------
    for (int idx = gtid; idx < BB * NPF; idx += NB * NT) {
        const float* r = xx + (size_t)idx * FIN;
        float* o = d_x + (size_t)idx * FC;
        int i1 = (int)fabsf(r[0]);
        int i2 = (int)fabsf(r[1]);
        int i3 = (int)fabsf(r[2]);
        o[0] = e1[i1 * 2]; o[1] = e1[i1 * 2 + 1];
        o[2] = e2[i2 * 2]; o[3] = e2[i2 * 2 + 1];
        o[4] = e3[i3 * 2]; o[5] = e3[i3 * 2 + 1];
#pragma unroll
        for (int f = 2; f < FIN; f++) {
            float v = r[f];
            if (f >= 3) {
                float y = __fdiv_rn(__fsub_rn(v, mean[f]), stdv[f]);
                y = fminf(fmaxf(y, -5.f), 5.f);
                float sc = __fdiv_rn(2.f, __fsub_rn(vmax[f], vmin[f]));
                y = __fsub_rn(__fmul_rn(sc, __fsub_rn(y, vmin[f])), 1.f);
                y = fminf(fmaxf(y, -1.f), 1.f);
                v = y;
            }
            o[6 + f - 2] = v;
        }
    }
    // -------- per-channel rsqrt (matches lax.rsqrt lowering) --------
    for (int idx = gtid; idx < NLL * HH; idx += NB * NT) {
        d_r[idx] = rsqrtf(__fadd_rn(mvar[idx], EPS_BN));
    }
    grid_bar();

    // -------- 100 sequential knn+MLP steps --------
#pragma unroll 1
    for (int it = 0; it < NPF; it++) {
        // ---- selection (blocks 0..31, one per batch element) ----
        if (bid < BB) {
            const int b = bid;
            const float* xb = d_x + (size_t)b * NPF * FC;
            float r0, r1;
            if (it == 0) {
                r0 = xb[12];  // ETA_C of particle 0
                r1 = xb[13];  // PHI_C
            } else {
                const float* hb = d_hA + (size_t)b * HH;
                double a0 = 0.0, a1 = 0.0;
                for (int k = tid; k < HH; k += NT) {
                    double hv = (double)hb[k];
                    a0 += hv * (double)Wc[2 * k];
                    a1 += hv * (double)Wc[2 * k + 1];
                }
                double* dred = (double*)s_red;     // 2048 doubles capacity
                dred[tid] = a0; dred[NT + tid] = a1;
                __syncthreads();
                for (int s = NT / 2; s > 0; s >>= 1) {
                    if (tid < s) {
                        dred[tid]      += dred[tid + s];
                        dred[NT + tid] += dred[NT + tid + s];
                    }
                    __syncthreads();
                }
                r0 = __fadd_rn((float)dred[0],  bc[0]);
                r1 = __fadd_rn((float)dred[NT], bc[1]);
                __syncthreads();
            }
            if (tid < NPF) {
                float de = __fsub_rn(xb[tid * FC + 12], r0);
                float dp = __fsub_rn(xb[tid * FC + 13], r1);
                s_sel[tid] = sqrtf(__fadd_rn(__fmul_rn(de, de), __fmul_rn(dp, dp)));
            }
            __syncthreads();
            if (tid == 0) {
                // stable top-11: smallest distance, ties -> smallest index
                for (int s = 0; s < KNN; s++) {
                    float best = CUDART_INF_F; int bi = 0;
                    for (int p = 0; p < NPF; p++) {
                        float v = s_sel[p];
                        if (v < best) { best = v; bi = p; }
                    }
                    s_idx[s] = bi;
                    s_sel[bi] = CUDART_INF_F;
                }
            }
            __syncthreads();
            for (int i = tid; i < KNN * FC; i += NT) {
                int s = i / FC, f = i % FC;
                int bi = s_idx[s];
                d_g[(size_t)b * (KNN * FC) + i] = xb[bi * FC + f];
            }
        }
        grid_bar();

        // ---- MLP: layer 0 (K=440, 11 tiles of 40), layers 1..4 (K=3600, 50 tiles of 72)
        gemm_layer<40, 11>(d_g, W0, d_hA, KNN * FC, 0,
                           b0, gamma, beta, mmean, s_w, s_xt, s_red);
        grid_bar();
        gemm_layer<72, 50>(d_hA, Wh,                   d_hB, HH, 1,
                           bh,        gamma + HH,   beta + HH,   mmean + HH,   s_w, s_xt, s_red); grid_bar();
        gemm_layer<72, 50>(d_hB, Wh + (size_t)1*HH*HH, d_hA, HH, 2,
                           bh + HH,   gamma + 2*HH, beta + 2*HH, mmean + 2*HH, s_w, s_xt, s_red); grid_bar();
        gemm_layer<72, 50>(d_hA, Wh + (size_t)2*HH*HH, d_hB, HH, 3,
                           bh + 2*HH, gamma + 3*HH, beta + 3*HH, mmean + 3*HH, s_w, s_xt, s_red); grid_bar();
        gemm_layer<72, 50>(d_hB, Wh + (size_t)3*HH*HH, d_hA, HH, 4,
                           bh + 3*HH, gamma + 4*HH, beta + 4*HH, mmean + 4*HH, s_w, s_xt, s_red); grid_bar();
    }

    // -------- final epilogue (blocks 0..31) --------
    if (bid < BB) {
        const int b = bid;
        const float* hb = d_hA + (size_t)b * HH;
        float* slog = s_sel;          // 100 logits
        float* sred = s_red;          // 256 reduce
        int w = tid >> 5, lane = tid & 31;

        // logits h @ W100 + b100
        for (int p = w; p < NPF; p += 8) {
            float acc = 0.f;
            for (int k = lane; k < HH; k += 32)
                acc += hb[k] * W100[(size_t)k * NPF + p];
#pragma unroll
            for (int o = 16; o; o >>= 1) acc += __shfl_down_sync(0xffffffffu, acc, o);
            if (lane == 0) slog[p] = acc + b100[p];
        }
        // x2 dots
        float a0 = 0.f, a1 = 0.f;
        for (int k = tid; k < HH; k += NT) {
            float hv = hb[k];
            a0 += hv * W2[2 * k];
            a1 += hv * W2[2 * k + 1];
        }
        __syncthreads();
        sred[tid] = a0; __syncthreads();
        for (int s = 128; s > 0; s >>= 1) { if (tid < s) sred[tid] += sred[tid + s]; __syncthreads(); }
        float x20 = sred[0] + b2[0]; __syncthreads();
        sred[tid] = a1; __syncthreads();
        for (int s = 128; s > 0; s >>= 1) { if (tid < s) sred[tid] += sred[tid + s]; __syncthreads(); }
        float x21 = sred[0] + b2[1]; __syncthreads();

        // softmax
        float mx = -CUDART_INF_F;
        for (int p = tid; p < NPF; p += NT) mx = fmaxf(mx, slog[p]);
        sred[tid] = mx; __syncthreads();
        for (int s = 128; s > 0; s >>= 1) { if (tid < s) sred[tid] = fmaxf(sred[tid], sred[tid + s]); __syncthreads(); }
        mx = sred[0]; __syncthreads();
        float es = 0.f;
        for (int p = tid; p < NPF; p += NT) {
            float e = expf(slog[p] - mx);
            slog[p] = e;
            es += e;
        }
        sred[tid] = es; __syncthreads();
        for (int s = 128; s > 0; s >>= 1) { if (tid < s) sred[tid] += sred[tid + s]; __syncthreads(); }
        es = sred[0]; __syncthreads();

        // weighted physics sums
        float px = 0.f, py = 0.f, pz = 0.f, E = 0.f;
        for (int p = tid; p < NPF; p += NT) {
            const float* xr = xx + ((size_t)b * NPF + p) * FIN;
            float wv = (slog[p] / es) * xr[7];
            px += xr[3] * wv; py += xr[4] * wv;
            pz += xr[5] * wv; E  += xr[6] * wv;
        }
        sred[tid] = px; __syncthreads();
        for (int s = 128; s > 0; s >>= 1) { if (tid < s) sred[tid] += sred[tid + s]; __syncthreads(); }
        px = sred[0]; __syncthreads();
        sred[tid] = py; __syncthreads();
        for (int s = 128; s > 0; s >>= 1) { if (tid < s) sred[tid] += sred[tid + s]; __syncthreads(); }
        py = sred[0]; __syncthreads();
        sred[tid] = pz; __syncthreads();
        for (int s = 128; s > 0; s >>= 1) { if (tid < s) sred[tid] += sred[tid + s]; __syncthreads(); }
        pz = sred[0]; __syncthreads();
        sred[tid] = E; __syncthreads();
        for (int s = 128; s > 0; s >>= 1) { if (tid < s) sred[tid] += sred[tid + s]; __syncthreads(); }
        E = sred[0]; __syncthreads();

        if (tid == 0) {
            float px2 = px * px, py2 = py * py, pz2 = pz * pz;
            float pt = sqrtf(px2 + py2);
            float mass2 = E * E - px2 - py2 - pz2;
            float absp = sqrtf(px2 + py2 + pz2);
            float cosT = (absp == 0.f) ? 1.f : pz / absp;
            bool okc = cosT * cosT < 1.f;
            float ratio = okc ? (1.f - cosT) / (1.f + cosT) : 1.f;
            float eta = okc ? -0.5f * logf(ratio) : 0.f;
            float phi = (px == 0.f && py == 0.f) ? 0.f : atan2f(py, px);
            out[b * 6 + 0] = x20;
            out[b * 6 + 1] = x21;
            out[b * 6 + 2] = pt;
            out[b * 6 + 3] = eta;
            out[b * 6 + 4] = phi;
            out[b * 6 + 5] = mass2;
        }
    }
}

// ---------------- launcher: ONE node in the graph ----------------
extern "C" void kernel_launch(void* const* d_in, const int* in_sizes, int n_in,
                              void* d_out, int out_size)
{
    mega_kernel<<<NB, NT>>>(
        (const float*)d_in[0],  (const float*)d_in[1],  (const float*)d_in[2],
        (const float*)d_in[3],  (const float*)d_in[4],  (const float*)d_in[5],
        (const float*)d_in[6],  (const float*)d_in[7],  (const float*)d_in[8],
        (const float*)d_in[9],  (const float*)d_in[10], (const float*)d_in[11],
        (const float*)d_in[12], (const float*)d_in[13], (const float*)d_in[14],
        (const float*)d_in[15], (const float*)d_in[16], (const float*)d_in[17],
        (const float*)d_in[18], (const float*)d_in[19], (const float*)d_in[20],
        (const float*)d_in[21], (float*)d_out);
}

// round 11
// speedup vs baseline: 2.4647x; 1.1307x over previous
#include <cuda_runtime.h>
#include <math_constants.h>

#define BB   32
#define NPF  100
#define FIN  36
#define KNN  11
#define FC   40
#define HH   3600
#define NLL  5
#define EPS_BN 1e-3f
#define NB   225          // grid blocks (225*16 = 3600 cols)
#define NT   256          // threads per block
#define NBUF 4            // cp.async ring depth (prefetch distance 3)

// ---------------- scratch (static, allocation-free) ----------------
__device__ float d_x[BB * NPF * FC];          // preprocessed features [b][p][f]
__device__ float d_gT[KNN * FC * BB];         // gathered knn features, transposed [k][b]
__device__ float d_hAT[HH * BB];              // hidden activations, transposed [k][b]
__device__ float d_hBT[HH * BB];
__device__ float d_r[NLL * HH];               // rsqrtf(mvar + eps)

__device__ unsigned bar_cnt = 0;
__device__ unsigned bar_gen = 0;

// grid-wide barrier: all NB blocks are co-resident by construction (NB=225 <= 2*148).
__device__ __forceinline__ void grid_bar()
{
    __syncthreads();
    if (threadIdx.x == 0) {
        __threadfence();
        unsigned gen = *((volatile unsigned*)&bar_gen);
        if (atomicAdd(&bar_cnt, 1u) == NB - 1) {
            bar_cnt = 0;
            __threadfence();
            *((volatile unsigned*)&bar_gen) = gen + 1;
        } else {
            while (*((volatile unsigned*)&bar_gen) == gen) __nanosleep(64);
        }
        __threadfence();
    }
    __syncthreads();
}

// ---------------- cp.async helpers ----------------
__device__ __forceinline__ void cp16(unsigned d, const void* s)
{
    asm volatile("cp.async.ca.shared.global [%0], [%1], 16;" :: "r"(d), "l"(s));
}
#define CP_COMMIT() asm volatile("cp.async.commit_group;")
#define CP_WAIT(N)  asm volatile("cp.async.wait_group %0;" :: "n"(N))

// packed fp32x2 FMA: two independent IEEE-rn FMAs (identical to scalar sequence)
__device__ __forceinline__ void ffma2(unsigned long long& acc,
                                      unsigned long long x2,
                                      unsigned long long w2)
{
    asm("fma.rn.f32x2 %0, %1, %2, %0;" : "+l"(acc) : "l"(x2), "l"(w2));
}
__device__ __forceinline__ unsigned long long add2(unsigned long long a,
                                                   unsigned long long b)
{
    unsigned long long r;
    asm("add.rn.f32x2 %0, %1, %2;" : "=l"(r) : "l"(a), "l"(b));
    return r;
}

// GEMM layer: (32 x KD) @ (KD x 3600), block owns 16 cols, 8 warps split K.
// inT is K-major transposed [KD][32] -> x tile is one contiguous block (cp16 only).
// 4-deep cp.async ring, FFMA2 inner loop. Accumulation order identical to the
// passing scalar/FFMA2 versions (same k->warp map, same A/B banks, double reduce).
template <int KT, int NTILE>
__device__ __forceinline__ void gemm_layer(const float* __restrict__ inT,
                                           const float* __restrict__ W,
                                           float* __restrict__ outT,
                                           int layer,
                                           const float* __restrict__ bias,
                                           const float* __restrict__ gamma,
                                           const float* __restrict__ beta,
                                           const float* __restrict__ mmean,
                                           float* s_w, float* s_xt, float* s_red)
{
    constexpr int SUB = KT / 8;       // k-values per warp per tile
    const int col0 = blockIdx.x * 16;
    const int tid  = threadIdx.x;
    const int w    = tid >> 5;
    const int lane = tid & 31;

    const unsigned sw_base = (unsigned)__cvta_generic_to_shared(s_w);
    const unsigned sx_base = (unsigned)__cvta_generic_to_shared(s_xt);

    unsigned long long accA[8], accB[8];
#pragma unroll
    for (int j = 0; j < 8; j++) { accA[j] = 0ull; accB[j] = 0ull; }

    // tile loader: W[KT][16] and contiguous x slab [KT][32], all 16B copies
    auto load_tile = [&](int buf, int t) {
        const int k0 = t * KT;
#pragma unroll 2
        for (int i = tid; i < KT * 4; i += NT) {
            int row = i >> 2, seg = i & 3;
            cp16(sw_base + (unsigned)(buf * KT * 16 + row * 16 + seg * 4) * 4,
                 W + (size_t)(k0 + row) * HH + col0 + seg * 4);
        }
#pragma unroll 3
        for (int i = tid; i < KT * 8; i += NT) {
            cp16(sx_base + (unsigned)(buf * KT * 32 + i * 4) * 4,
                 inT + (size_t)k0 * 32 + i * 4);
        }
        CP_COMMIT();
    };

    // prime the ring: tiles 0..2 (3 groups outstanding)
    load_tile(0, 0);
    load_tile(1, 1);
    load_tile(2, 2);

#pragma unroll 1
    for (int t = 0; t < NTILE; t++) {
        // keep exactly one group per loop iteration (empty commit in the tail)
        if (t + 3 < NTILE) load_tile((t + 3) & (NBUF - 1), t + 3);
        else               CP_COMMIT();
        CP_WAIT(3);                    // tile t's group retired
        __syncthreads();

        const int buf = t & (NBUF - 1);
        const float* xk = s_xt + buf * KT * 32;
        const float* wk = s_w + buf * KT * 16;
        const int kbase = w * SUB;

#pragma unroll
        for (int kk = 0; kk < SUB; kk++) {
            const int k = kbase + kk;
            float xv = xk[k * 32 + lane];
            unsigned long long x2;
            asm("mov.b64 %0, {%1, %1};" : "=l"(x2) : "f"(xv));
            const ulonglong2* wp = (const ulonglong2*)(wk + k * 16);
            ulonglong2 q0 = wp[0], q1 = wp[1], q2 = wp[2], q3 = wp[3];
            unsigned long long* acc = (kk & 1) ? accB : accA;
            ffma2(acc[0], x2, q0.x); ffma2(acc[1], x2, q0.y);
            ffma2(acc[2], x2, q1.x); ffma2(acc[3], x2, q1.y);
            ffma2(acc[4], x2, q2.x); ffma2(acc[5], x2, q2.y);
            ffma2(acc[6], x2, q3.x); ffma2(acc[7], x2, q3.y);
        }
        __syncthreads();
    }

    // per-warp partial = A + B (packed add = identical scalar adds)
#pragma unroll
    for (int j = 0; j < 8; j++) {
        unsigned long long s2 = add2(accA[j], accB[j]);
        unsigned lo, hi;
        asm("mov.b64 {%0, %1}, %2;" : "=r"(lo), "=r"(hi) : "l"(s2));
        s_red[w * 512 + lane * 16 + 2 * j]     = __uint_as_float(lo);
        s_red[w * 512 + lane * 16 + 2 * j + 1] = __uint_as_float(hi);
    }
    __syncthreads();
    for (int o = tid; o < 512; o += NT) {
        double s = 0.0;
#pragma unroll
        for (int ww = 0; ww < 8; ww++) s += (double)s_red[ww * 512 + o];
        int row = o >> 4, c = o & 15;
        int col = col0 + c;
        float sf = (float)s;
        // reference op order: h = dot + bias; u = h - mmean; v = ((gamma*u)*r) + beta
        float h1 = __fadd_rn(sf, bias[col]);
        float u  = __fsub_rn(h1, mmean[col]);
        float v  = __fadd_rn(__fmul_rn(__fmul_rn(gamma[col], u),
                                       d_r[layer * HH + col]),
                             beta[col]);
        outT[(size_t)col * 32 + row] = fmaxf(v, 0.f);
    }
    __syncthreads();
}

__global__ void __launch_bounds__(NT, 2)
mega_kernel(const float* __restrict__ xx,
            const float* __restrict__ e1, const float* __restrict__ e2,
            const float* __restrict__ e3,
            const float* __restrict__ mean, const float* __restrict__ stdv,
            const float* __restrict__ vmin, const float* __restrict__ vmax,
            const float* __restrict__ W0,  const float* __restrict__ b0,
            const float* __restrict__ Wh,  const float* __restrict__ bh,
            const float* __restrict__ gamma, const float* __restrict__ beta,
            const float* __restrict__ mmean, const float* __restrict__ mvar,
            const float* __restrict__ Wc,  const float* __restrict__ bc,
            const float* __restrict__ W2,  const float* __restrict__ b2,
            const float* __restrict__ W100,const float* __restrict__ b100,
            float* __restrict__ out)
{
    extern __shared__ __align__(16) float smem_dyn[];
    float* s_w   = smem_dyn;                       // NBUF * 72*16 = 4608
    float* s_xt  = s_w + NBUF * 72 * 16;           // NBUF * 72*32 = 9216
    float* s_red = s_xt + NBUF * 72 * 32;          // 4096 (8B aligned for double use)
    float* s_sel = s_red + 4096;                   // 128
    int*   s_idx = (int*)(s_sel + 128);            // 16

    const int bid = blockIdx.x;
    const int tid = threadIdx.x;
    const int gtid = bid * NT + tid;

    // -------- preprocessing (contraction-free IEEE ops) --------
    for (int idx = gtid; idx < BB * NPF; idx += NB * NT) {
        const float* r = xx + (size_t)idx * FIN;
        float* o = d_x + (size_t)idx * FC;
        int i1 = (int)fabsf(r[0]);
        int i2 = (int)fabsf(r[1]);
        int i3 = (int)fabsf(r[2]);
        o[0] = e1[i1 * 2]; o[1] = e1[i1 * 2 + 1];
        o[2] = e2[i2 * 2]; o[3] = e2[i2 * 2 + 1];
        o[4] = e3[i3 * 2]; o[5] = e3[i3 * 2 + 1];
#pragma unroll
        for (int f = 2; f < FIN; f++) {
            float v = r[f];
            if (f >= 3) {
                float y = __fdiv_rn(__fsub_rn(v, mean[f]), stdv[f]);
                y = fminf(fmaxf(y, -5.f), 5.f);
                float sc = __fdiv_rn(2.f, __fsub_rn(vmax[f], vmin[f]));
                y = __fsub_rn(__fmul_rn(sc, __fsub_rn(y, vmin[f])), 1.f);
                y = fminf(fmaxf(y, -1.f), 1.f);
                v = y;
            }
            o[6 + f - 2] = v;
        }
    }
    // -------- per-channel rsqrt (matches lax.rsqrt lowering) --------
    for (int idx = gtid; idx < NLL * HH; idx += NB * NT) {
        d_r[idx] = rsqrtf(__fadd_rn(mvar[idx], EPS_BN));
    }
    grid_bar();

    // -------- 100 sequential knn+MLP steps --------
#pragma unroll 1
    for (int it = 0; it < NPF; it++) {
        // ---- selection (blocks 0..31, one per batch element) ----
        if (bid < BB) {
            const int b = bid;
            const float* xb = d_x + (size_t)b * NPF * FC;
            float r0, r1;
            if (it == 0) {
                r0 = xb[12];  // ETA_C of particle 0
                r1 = xb[13];  // PHI_C
            } else {
                double a0 = 0.0, a1 = 0.0;
                for (int k = tid; k < HH; k += NT) {
                    double hv = (double)d_hAT[(size_t)k * 32 + b];
                    a0 += hv * (double)Wc[2 * k];
                    a1 += hv * (double)Wc[2 * k + 1];
                }
                double* dred = (double*)s_red;     // 2048 doubles capacity
                dred[tid] = a0; dred[NT + tid] = a1;
                __syncthreads();
                for (int s = NT / 2; s > 0; s >>= 1) {
                    if (tid < s) {
                        dred[tid]      += dred[tid + s];
                        dred[NT + tid] += dred[NT + tid + s];
                    }
                    __syncthreads();
                }
                r0 = __fadd_rn((float)dred[0],  bc[0]);
                r1 = __fadd_rn((float)dred[NT], bc[1]);
                __syncthreads();
            }
            if (tid < NPF) {
                float de = __fsub_rn(xb[tid * FC + 12], r0);
                float dp = __fsub_rn(xb[tid * FC + 13], r1);
                s_sel[tid] = sqrtf(__fadd_rn(__fmul_rn(de, de), __fmul_rn(dp, dp)));
            }
            __syncthreads();
            // warp-parallel stable top-11 (exact (d, idx) order -> identical picks)
            if (tid < 32) {
                const int lane = tid;
#pragma unroll 1
                for (int s = 0; s < KNN; s++) {
                    float best = CUDART_INF_F; int bi = NPF;
                    for (int p = lane; p < NPF; p += 32) {
                        float v = s_sel[p];
                        if (v < best || (v == best && p < bi)) { best = v; bi = p; }
                    }
#pragma unroll
                    for (int o = 16; o; o >>= 1) {
                        float ov = __shfl_down_sync(0xffffffffu, best, o);
                        int   oi = __shfl_down_sync(0xffffffffu, bi, o);
                        if (ov < best || (ov == best && oi < bi)) { best = ov; bi = oi; }
                    }
                    bi = __shfl_sync(0xffffffffu, bi, 0);
                    if (lane == 0) { s_idx[s] = bi; s_sel[bi] = CUDART_INF_F; }
                    __syncwarp();
                }
            }
            __syncthreads();
            // gather into transposed layout [440][32]
            for (int i = tid; i < KNN * FC; i += NT) {
                int s = i / FC, f = i - s * FC;
                d_gT[(size_t)i * 32 + b] = xb[s_idx[s] * FC + f];
            }
        }
        grid_bar();

        // ---- MLP: layer 0 (K=440, 11 tiles of 40), layers 1..4 (K=3600, 50 tiles of 72)
        gemm_layer<40, 11>(d_gT, W0, d_hAT, 0,
                           b0, gamma, beta, mmean, s_w, s_xt, s_red);
        grid_bar();
        gemm_layer<72, 50>(d_hAT, Wh,                   d_hBT, 1,
                           bh,        gamma + HH,   beta + HH,   mmean + HH,   s_w, s_xt, s_red); grid_bar();
        gemm_layer<72, 50>(d_hBT, Wh + (size_t)1*HH*HH, d_hAT, 2,
                           bh + HH,   gamma + 2*HH, beta + 2*HH, mmean + 2*HH, s_w, s_xt, s_red); grid_bar();
        gemm_layer<72, 50>(d_hAT, Wh + (size_t)2*HH*HH, d_hBT, 3,
                           bh + 2*HH, gamma + 3*HH, beta + 3*HH, mmean + 3*HH, s_w, s_xt, s_red); grid_bar();
        gemm_layer<72, 50>(d_hBT, Wh + (size_t)3*HH*HH, d_hAT, 4,
                           bh + 3*HH, gamma + 4*HH, beta + 4*HH, mmean + 4*HH, s_w, s_xt, s_red); grid_bar();
    }

    // -------- final epilogue (blocks 0..31) --------
    if (bid < BB) {
        const int b = bid;
        float* slog = s_sel;          // 100 logits
        float* sred = s_red;          // 256 reduce
        int w = tid >> 5, lane = tid & 31;

        // logits h @ W100 + b100
        for (int p = w; p < NPF; p += 8) {
            float acc = 0.f;
            for (int k = lane; k < HH; k += 32)
                acc += d_hAT[(size_t)k * 32 + b] * W100[(size_t)k * NPF + p];
#pragma unroll
            for (int o = 16; o; o >>= 1) acc += __shfl_down_sync(0xffffffffu, acc, o);
            if (lane == 0) slog[p] = acc + b100[p];
        }
        // x2 dots
        float a0 = 0.f, a1 = 0.f;
        for (int k = tid; k < HH; k += NT) {
            float hv = d_hAT[(size_t)k * 32 + b];
            a0 += hv * W2[2 * k];
            a1 += hv * W2[2 * k + 1];
        }
        __syncthreads();
        sred[tid] = a0; __syncthreads();
        for (int s = 128; s > 0; s >>= 1) { if (tid < s) sred[tid] += sred[tid + s]; __syncthreads(); }
        float x20 = sred[0] + b2[0]; __syncthreads();
        sred[tid] = a1; __syncthreads();
        for (int s = 128; s > 0; s >>= 1) { if (tid < s) sred[tid] += sred[tid + s]; __syncthreads(); }
        float x21 = sred[0] + b2[1]; __syncthreads();

        // softmax
        float mx = -CUDART_INF_F;
        for (int p = tid; p < NPF; p += NT) mx = fmaxf(mx, slog[p]);
        sred[tid] = mx; __syncthreads();
        for (int s = 128; s > 0; s >>= 1) { if (tid < s) sred[tid] = fmaxf(sred[tid], sred[tid + s]); __syncthreads(); }
        mx = sred[0]; __syncthreads();
        float es = 0.f;
        for (int p = tid; p < NPF; p += NT) {
            float e = expf(slog[p] - mx);
            slog[p] = e;
            es += e;
        }
        sred[tid] = es; __syncthreads();
        for (int s = 128; s > 0; s >>= 1) { if (tid < s) sred[tid] += sred[tid + s]; __syncthreads(); }
        es = sred[0]; __syncthreads();

        // weighted physics sums
        float px = 0.f, py = 0.f, pz = 0.f, E = 0.f;
        for (int p = tid; p < NPF; p += NT) {
            const float* xr = xx + ((size_t)b * NPF + p) * FIN;
            float wv = (slog[p] / es) * xr[7];
            px += xr[3] * wv; py += xr[4] * wv;
            pz += xr[5] * wv; E  += xr[6] * wv;
        }
        sred[tid] = px; __syncthreads();
        for (int s = 128; s > 0; s >>= 1) { if (tid < s) sred[tid] += sred[tid + s]; __syncthreads(); }
        px = sred[0]; __syncthreads();
        sred[tid] = py; __syncthreads();
        for (int s = 128; s > 0; s >>= 1) { if (tid < s) sred[tid] += sred[tid + s]; __syncthreads(); }
        py = sred[0]; __syncthreads();
        sred[tid] = pz; __syncthreads();
        for (int s = 128; s > 0; s >>= 1) { if (tid < s) sred[tid] += sred[tid + s]; __syncthreads(); }
        pz = sred[0]; __syncthreads();
        sred[tid] = E; __syncthreads();
        for (int s = 128; s > 0; s >>= 1) { if (tid < s) sred[tid] += sred[tid + s]; __syncthreads(); }
        E = sred[0]; __syncthreads();

        if (tid == 0) {
            float px2 = px * px, py2 = py * py, pz2 = pz * pz;
            float pt = sqrtf(px2 + py2);
            float mass2 = E * E - px2 - py2 - pz2;
            float absp = sqrtf(px2 + py2 + pz2);
            float cosT = (absp == 0.f) ? 1.f : pz / absp;
            bool okc = cosT * cosT < 1.f;
            float ratio = okc ? (1.f - cosT) / (1.f + cosT) : 1.f;
            float eta = okc ? -0.5f * logf(ratio) : 0.f;
            float phi = (px == 0.f && py == 0.f) ? 0.f : atan2f(py, px);
            out[b * 6 + 0] = x20;
            out[b * 6 + 1] = x21;
            out[b * 6 + 2] = pt;
            out[b * 6 + 3] = eta;
            out[b * 6 + 4] = phi;
            out[b * 6 + 5] = mass2;
        }
    }
}

// ---------------- launcher: ONE node in the graph ----------------
extern "C" void kernel_launch(void* const* d_in, const int* in_sizes, int n_in,
                              void* d_out, int out_size)
{
    // dynamic smem: NBUF*(72*16 + 72*32) + 4096 + 128 + 16 ints
    const int smem_bytes = (NBUF * 72 * 16 + NBUF * 72 * 32 + 4096 + 128 + 16) * 4;
    static int attr_done = 0;
    if (!attr_done) {
        cudaFuncSetAttribute(mega_kernel,
                             cudaFuncAttributeMaxDynamicSharedMemorySize, smem_bytes);
        attr_done = 1;
    }
    mega_kernel<<<NB, NT, smem_bytes>>>(
        (const float*)d_in[0],  (const float*)d_in[1],  (const float*)d_in[2],
        (const float*)d_in[3],  (const float*)d_in[4],  (const float*)d_in[5],
        (const float*)d_in[6],  (const float*)d_in[7],  (const float*)d_in[8],
        (const float*)d_in[9],  (const float*)d_in[10], (const float*)d_in[11],
        (const float*)d_in[12], (const float*)d_in[13], (const float*)d_in[14],
        (const float*)d_in[15], (const float*)d_in[16], (const float*)d_in[17],
        (const float*)d_in[18], (const float*)d_in[19], (const float*)d_in[20],
        (const float*)d_in[21], (float*)d_out);
}

// round 14
// speedup vs baseline: 3.2150x; 1.3044x over previous
#include <cuda_runtime.h>
#include <math_constants.h>

#define BB   32
#define NPF  100
#define FIN  36
#define KNN  11
#define FC   40
#define HH   3600
#define NLL  5
#define EPS_BN 1e-3f
#define NB   225          // grid blocks (225*16 = 3600 cols)
#define NT   256          // threads per block
#define NBUF 2            // cp.async ring depth (prefetch distance 1)

// ---------------- scratch (static, allocation-free) ----------------
__device__ float  d_x[BB * NPF * FC];          // preprocessed features [b][p][f]
__device__ float  d_gT[KNN * FC * BB];         // gathered knn features, transposed [k][b]
__device__ float  d_hAT[HH * BB];              // hidden activations, transposed [k][b]
__device__ float  d_hBT[HH * BB];
__device__ float  d_r[NLL * HH];               // rsqrtf(mvar + eps)
__device__ double d_c2part[BB * NB * 2];       // per-block c2 partials [b][blk][2]

__device__ unsigned bar_cnt = 0;
__device__ unsigned bar_gen = 0;

// grid-wide barrier: all NB blocks are co-resident by construction (NB=225 <= 2*148).
__device__ __forceinline__ void grid_bar()
{
    __syncthreads();
    if (threadIdx.x == 0) {
        __threadfence();
        unsigned gen = *((volatile unsigned*)&bar_gen);
        if (atomicAdd(&bar_cnt, 1u) == NB - 1) {
            bar_cnt = 0;
            __threadfence();
            *((volatile unsigned*)&bar_gen) = gen + 1;
        } else {
            while (*((volatile unsigned*)&bar_gen) == gen) __nanosleep(64);
        }
        __threadfence();
    }
    __syncthreads();
}

// ---------------- cp.async helpers ----------------
__device__ __forceinline__ void cp16(unsigned d, const void* s)
{
    asm volatile("cp.async.ca.shared.global [%0], [%1], 16;" :: "r"(d), "l"(s));
}
#define CP_COMMIT() asm volatile("cp.async.commit_group;")
#define CP_WAIT(N)  asm volatile("cp.async.wait_group %0;" :: "n"(N))

// packed fp32x2 FMA: two independent IEEE-rn FMAs (identical to scalar sequence)
__device__ __forceinline__ void ffma2(unsigned long long& acc,
                                      unsigned long long x2,
                                      unsigned long long w2)
{
    asm("fma.rn.f32x2 %0, %1, %2, %0;" : "+l"(acc) : "l"(x2), "l"(w2));
}
__device__ __forceinline__ unsigned long long add2(unsigned long long a,
                                                   unsigned long long b)
{
    unsigned long long r;
    asm("add.rn.f32x2 %0, %1, %2;" : "=l"(r) : "l"(a), "l"(b));
    return r;
}

// GEMM layer: (32 x KD) @ (KD x 3600), block owns 16 cols, 8 warps split K.
// 4x4 register tiling: lane = rg*4+cg -> thread owns rows rg*4..+3, cols cg*4..+3.
// Per k: 1 x-wavefront (128B LDS.128) + 1 W-wavefront (LDS.128 broadcast).
// Per-accumulator FMA sequence (k order + even/odd A/B banks) is IDENTICAL to the
// passing version -> warp partials bitwise identical; double cross-warp reduce;
// unfolded BN in reference op order.
template <int KT, int NTILE>
__device__ __forceinline__ void gemm_layer(const float* __restrict__ inT,
                                           const float* __restrict__ W,
                                           float* __restrict__ outT,
                                           int layer,
                                           const float* __restrict__ bias,
                                           const float* __restrict__ gamma,
                                           const float* __restrict__ beta,
                                           const float* __restrict__ mmean,
                                           const float* __restrict__ Wc, int do_c2,
                                           float* s_w, float* s_xt, float* s_red)
{
    constexpr int SUB = KT / 8;       // k-values per warp per tile
    const int col0 = blockIdx.x * 16;
    const int tid  = threadIdx.x;
    const int w    = tid >> 5;
    const int lane = tid & 31;
    const int rg   = lane >> 2;       // row group (0..7) -> rows rg*4..+3
    const int cg   = lane & 3;        // col group (0..3) -> cols cg*4..+3

    const unsigned sw_base = (unsigned)__cvta_generic_to_shared(s_w);
    const unsigned sx_base = (unsigned)__cvta_generic_to_shared(s_xt);

    // acc[r][cp]: r = row within group, cp = col pair within group (cols cg*4+2cp, +1)
    unsigned long long accA[4][2], accB[4][2];
#pragma unroll
    for (int r = 0; r < 4; r++)
#pragma unroll
        for (int cp = 0; cp < 2; cp++) { accA[r][cp] = 0ull; accB[r][cp] = 0ull; }

    // tile loader: W[KT][16] and contiguous x slab [KT][32], all 16B copies
    auto load_tile = [&](int buf, int t) {
        const int k0 = t * KT;
#pragma unroll 3
        for (int i = tid; i < KT * 4; i += NT) {
            int row = i >> 2, seg = i & 3;
            cp16(sw_base + (unsigned)(buf * KT * 16 + row * 16 + seg * 4) * 4,
                 W + (size_t)(k0 + row) * HH + col0 + seg * 4);
        }
#pragma unroll 5
        for (int i = tid; i < KT * 8; i += NT) {
            cp16(sx_base + (unsigned)(buf * KT * 32 + i * 4) * 4,
                 inT + (size_t)k0 * 32 + i * 4);
        }
        CP_COMMIT();
    };

    load_tile(0, 0);

#pragma unroll 1
    for (int t = 0; t < NTILE; t++) {
        if (t + 1 < NTILE) load_tile((t + 1) & 1, t + 1);
        else               CP_COMMIT();
        CP_WAIT(1);                    // tile t's group retired
        __syncthreads();

        const int buf = t & 1;
        const float* xp = s_xt + buf * KT * 32 + (w * SUB) * 32 + rg * 4;
        const float* wp = s_w  + buf * KT * 16 + (w * SUB) * 16 + cg * 4;

#pragma unroll 6
        for (int kk = 0; kk < SUB; kk++) {
            float4 xv = *(const float4*)xp;
            ulonglong2 wv = *(const ulonglong2*)wp;
            unsigned long long x2[4];
            asm("mov.b64 %0, {%1, %1};" : "=l"(x2[0]) : "f"(xv.x));
            asm("mov.b64 %0, {%1, %1};" : "=l"(x2[1]) : "f"(xv.y));
            asm("mov.b64 %0, {%1, %1};" : "=l"(x2[2]) : "f"(xv.z));
            asm("mov.b64 %0, {%1, %1};" : "=l"(x2[3]) : "f"(xv.w));
            if (kk & 1) {
#pragma unroll
                for (int r = 0; r < 4; r++) {
                    ffma2(accB[r][0], x2[r], wv.x);
                    ffma2(accB[r][1], x2[r], wv.y);
                }
            } else {
#pragma unroll
                for (int r = 0; r < 4; r++) {
                    ffma2(accA[r][0], x2[r], wv.x);
                    ffma2(accA[r][1], x2[r], wv.y);
                }
            }
            xp += 32; wp += 16;
        }
        __syncthreads();
    }

    // per-warp partial = A + B (packed add = identical scalar adds); layout [w][row][col]
#pragma unroll
    for (int r = 0; r < 4; r++)
#pragma unroll
        for (int cp = 0; cp < 2; cp++) {
            unsigned long long s2 = add2(accA[r][cp], accB[r][cp]);
            unsigned lo, hi;
            asm("mov.b64 {%0, %1}, %2;" : "=r"(lo), "=r"(hi) : "l"(s2));
            int row = rg * 4 + r, c = cg * 4 + 2 * cp;
            s_red[w * 512 + row * 16 + c]     = __uint_as_float(lo);
            s_red[w * 512 + row * 16 + c + 1] = __uint_as_float(hi);
        }
    __syncthreads();
#pragma unroll 1
    for (int o = tid; o < 512; o += NT) {
        double s = 0.0;
#pragma unroll
        for (int ww = 0; ww < 8; ww++) s += (double)s_red[ww * 512 + o];
        int row = o >> 4, c = o & 15;
        int col = col0 + c;
        float sf = (float)s;
        // reference op order: h = dot + bias; u = h - mmean; v = ((gamma*u)*r) + beta
        float h1 = __fadd_rn(sf, bias[col]);
        float u  = __fsub_rn(h1, mmean[col]);
        float v  = __fadd_rn(__fmul_rn(__fmul_rn(gamma[col], u),
                                       d_r[layer * HH + col]),
                             beta[col]);
        v = fmaxf(v, 0.f);
        outT[(size_t)col * 32 + row] = v;
        if (do_c2) {
            // fold c2 partial: sum over this block's 16 cols (fp64, shfl tree)
            double p0 = (double)v * (double)Wc[2 * col];
            double p1 = (double)v * (double)Wc[2 * col + 1];
#pragma unroll
            for (int off = 8; off; off >>= 1) {
                p0 += __shfl_down_sync(0xffffffffu, p0, off, 16);
                p1 += __shfl_down_sync(0xffffffffu, p1, off, 16);
            }
            if ((o & 15) == 0) {
                d_c2part[((size_t)row * NB + blockIdx.x) * 2 + 0] = p0;
                d_c2part[((size_t)row * NB + blockIdx.x) * 2 + 1] = p1;
            }
        }
    }
    __syncthreads();
}

__global__ void __launch_bounds__(NT, 2)
mega_kernel(const float* __restrict__ xx,
            const float* __restrict__ e1, const float* __restrict__ e2,
            const float* __restrict__ e3,
            const float* __restrict__ mean, const float* __restrict__ stdv,
            const float* __restrict__ vmin, const float* __restrict__ vmax,
            const float* __restrict__ W0,  const float* __restrict__ b0,
            const float* __restrict__ Wh,  const float* __restrict__ bh,
            const float* __restrict__ gamma, const float* __restrict__ beta,
            const float* __restrict__ mmean, const float* __restrict__ mvar,
            const float* __restrict__ Wc,  const float* __restrict__ bc,
            const float* __restrict__ W2,  const float* __restrict__ b2,
            const float* __restrict__ W100,const float* __restrict__ b100,
            float* __restrict__ out)
{
    extern __shared__ __align__(16) float smem_dyn[];
    float* s_w   = smem_dyn;                       // NBUF * 144*16 = 4608
    float* s_xt  = s_w + NBUF * 144 * 16;          // NBUF * 144*32 = 9216
    float* s_red = s_xt + NBUF * 144 * 32;         // 4096 (8B aligned for double use)
    float* s_sel = s_red + 4096;                   // 128
    int*   s_idx = (int*)(s_sel + 128);            // 16

    const int bid = blockIdx.x;
    const int tid = threadIdx.x;
    const int gtid = bid * NT + tid;

    // -------- preprocessing (contraction-free IEEE ops) --------
    for (int idx = gtid; idx < BB * NPF; idx += NB * NT) {
        const float* r = xx + (size_t)idx * FIN;
        float* o = d_x + (size_t)idx * FC;
        int i1 = (int)fabsf(r[0]);
        int i2 = (int)fabsf(r[1]);
        int i3 = (int)fabsf(r[2]);
        o[0] = e1[i1 * 2]; o[1] = e1[i1 * 2 + 1];
        o[2] = e2[i2 * 2]; o[3] = e2[i2 * 2 + 1];
        o[4] = e3[i3 * 2]; o[5] = e3[i3 * 2 + 1];
#pragma unroll
        for (int f = 2; f < FIN; f++) {
            float v = r[f];
            if (f >= 3) {
                float y = __fdiv_rn(__fsub_rn(v, mean[f]), stdv[f]);
                y = fminf(fmaxf(y, -5.f), 5.f);
                float sc = __fdiv_rn(2.f, __fsub_rn(vmax[f], vmin[f]));
                y = __fsub_rn(__fmul_rn(sc, __fsub_rn(y, vmin[f])), 1.f);
                y = fminf(fmaxf(y, -1.f), 1.f);
                v = y;
            }
            o[6 + f - 2] = v;
        }
    }
    // -------- per-channel rsqrt (matches lax.rsqrt lowering) --------
    for (int idx = gtid; idx < NLL * HH; idx += NB * NT) {
        d_r[idx] = rsqrtf(__fadd_rn(mvar[idx], EPS_BN));
    }
    grid_bar();

    // -------- 100 sequential knn+MLP steps --------
#pragma unroll 1
    for (int it = 0; it < NPF; it++) {
        // ---- selection (blocks 0..31, one per batch element) ----
        if (bid < BB) {
            const int b = bid;
            const float* xb = d_x + (size_t)b * NPF * FC;
            float r0, r1;
            if (it == 0) {
                r0 = xb[12];  // ETA_C of particle 0
                r1 = xb[13];  // PHI_C
            } else {
                // deterministic fp64 tree over the 225 per-block partials
                double* dred = (double*)s_red;
                double v0 = 0.0, v1 = 0.0;
                if (tid < NB) {
                    v0 = d_c2part[((size_t)b * NB + tid) * 2 + 0];
                    v1 = d_c2part[((size_t)b * NB + tid) * 2 + 1];
                }
                dred[tid] = v0; dred[NT + tid] = v1;
                __syncthreads();
                for (int s = NT / 2; s > 0; s >>= 1) {
                    if (tid < s) {
                        dred[tid]      += dred[tid + s];
                        dred[NT + tid] += dred[NT + tid + s];
                    }
                    __syncthreads();
                }
                r0 = __fadd_rn((float)dred[0],  bc[0]);
                r1 = __fadd_rn((float)dred[NT], bc[1]);
                __syncthreads();
            }
            if (tid < NPF) {
                float de = __fsub_rn(xb[tid * FC + 12], r0);
                float dp = __fsub_rn(xb[tid * FC + 13], r1);
                s_sel[tid] = sqrtf(__fadd_rn(__fmul_rn(de, de), __fmul_rn(dp, dp)));
            }
            __syncthreads();
            // warp-parallel stable top-11 (exact (d, idx) order -> identical picks)
            if (tid < 32) {
                const int lane = tid;
#pragma unroll 1
                for (int s = 0; s < KNN; s++) {
                    float best = CUDART_INF_F; int bi = NPF;
                    for (int p = lane; p < NPF; p += 32) {
                        float v = s_sel[p];
                        if (v < best || (v == best && p < bi)) { best = v; bi = p; }
                    }
#pragma unroll
                    for (int o = 16; o; o >>= 1) {
                        float ov = __shfl_down_sync(0xffffffffu, best, o);
                        int   oi = __shfl_down_sync(0xffffffffu, bi, o);
                        if (ov < best || (ov == best && oi < bi)) { best = ov; bi = oi; }
                    }
                    bi = __shfl_sync(0xffffffffu, bi, 0);
                    if (lane == 0) { s_idx[s] = bi; s_sel[bi] = CUDART_INF_F; }
                    __syncwarp();
                }
            }
            __syncthreads();
            // gather into transposed layout [440][32]
            for (int i = tid; i < KNN * FC; i += NT) {
                int s = i / FC, f = i - s * FC;
                d_gT[(size_t)i * 32 + b] = xb[s_idx[s] * FC + f];
            }
        }
        grid_bar();

        // ---- MLP: layer 0 (K=440, 11 tiles of 40), layers 1..4 (K=3600, 25 tiles of 144)
        gemm_layer<40, 11>(d_gT, W0, d_hAT, 0,
                           b0, gamma, beta, mmean, Wc, 0, s_w, s_xt, s_red);
        grid_bar();
        gemm_layer<144, 25>(d_hAT, Wh,                   d_hBT, 1,
                            bh,        gamma + HH,   beta + HH,   mmean + HH,
                            Wc, 0, s_w, s_xt, s_red); grid_bar();
        gemm_layer<144, 25>(d_hBT, Wh + (size_t)1*HH*HH, d_hAT, 2,
                            bh + HH,   gamma + 2*HH, beta + 2*HH, mmean + 2*HH,
                            Wc, 0, s_w, s_xt, s_red); grid_bar();
        gemm_layer<144, 25>(d_hAT, Wh + (size_t)2*HH*HH, d_hBT, 3,
                            bh + 2*HH, gamma + 3*HH, beta + 3*HH, mmean + 3*HH,
                            Wc, 0, s_w, s_xt, s_red); grid_bar();
        gemm_layer<144, 25>(d_hBT, Wh + (size_t)3*HH*HH, d_hAT, 4,
                            bh + 3*HH, gamma + 4*HH, beta + 4*HH, mmean + 4*HH,
                            Wc, 1, s_w, s_xt, s_red); grid_bar();
    }

    // -------- final epilogue (blocks 0..31) --------
    if (bid < BB) {
        const int b = bid;
        float* slog = s_sel;          // 100 logits
        float* sred = s_red;          // 256 reduce
        int w = tid >> 5, lane = tid & 31;

        // logits h @ W100 + b100
        for (int p = w; p < NPF; p += 8) {
            float acc = 0.f;
            for (int k = lane; k < HH; k += 32)
                acc += d_hAT[(size_t)k * 32 + b] * W100[(size_t)k * NPF + p];
#pragma unroll
            for (int o = 16; o; o >>= 1) acc += __shfl_down_sync(0xffffffffu, acc, o);
            if (lane == 0) slog[p] = acc + b100[p];
        }
        // x2 dots
        float a0 = 0.f, a1 = 0.f;
        for (int k = tid; k < HH; k += NT) {
            float hv = d_hAT[(size_t)k * 32 + b];
            a0 += hv * W2[2 * k];
            a1 += hv * W2[2 * k + 1];
        }
        __syncthreads();
        sred[tid] = a0; __syncthreads();
        for (int s = 128; s > 0; s >>= 1) { if (tid < s) sred[tid] += sred[tid + s]; __syncthreads(); }
        float x20 = sred[0] + b2[0]; __syncthreads();
        sred[tid] = a1; __syncthreads();
        for (int s = 128; s > 0; s >>= 1) { if (tid < s) sred[tid] += sred[tid + s]; __syncthreads(); }
        float x21 = sred[0] + b2[1]; __syncthreads();

        // softmax
        float mx = -CUDART_INF_F;
        for (int p = tid; p < NPF; p += NT) mx = fmaxf(mx, slog[p]);
        sred[tid] = mx; __syncthreads();
        for (int s = 128; s > 0; s >>= 1) { if (tid < s) sred[tid] = fmaxf(sred[tid], sred[tid + s]); __syncthreads(); }
        mx = sred[0]; __syncthreads();
        float es = 0.f;
        for (int p = tid; p < NPF; p += NT) {
            float e = expf(slog[p] - mx);
            slog[p] = e;
            es += e;
        }
        sred[tid] = es; __syncthreads();
        for (int s = 128; s > 0; s >>= 1) { if (tid < s) sred[tid] += sred[tid + s]; __syncthreads(); }
        es = sred[0]; __syncthreads();

        // weighted physics sums
        float px = 0.f, py = 0.f, pz = 0.f, E = 0.f;
        for (int p = tid; p < NPF; p += NT) {
            const float* xr = xx + ((size_t)b * NPF + p) * FIN;
            float wv = (slog[p] / es) * xr[7];
            px += xr[3] * wv; py += xr[4] * wv;
            pz += xr[5] * wv; E  += xr[6] * wv;
        }
        sred[tid] = px; __syncthreads();
        for (int s = 128; s > 0; s >>= 1) { if (tid < s) sred[tid] += sred[tid + s]; __syncthreads(); }
        px = sred[0]; __syncthreads();
        sred[tid] = py; __syncthreads();
        for (int s = 128; s > 0; s >>= 1) { if (tid < s) sred[tid] += sred[tid + s]; __syncthreads(); }
        py = sred[0]; __syncthreads();
        sred[tid] = pz; __syncthreads();
        for (int s = 128; s > 0; s >>= 1) { if (tid < s) sred[tid] += sred[tid + s]; __syncthreads(); }
        pz = sred[0]; __syncthreads();
        sred[tid] = E; __syncthreads();
        for (int s = 128; s > 0; s >>= 1) { if (tid < s) sred[tid] += sred[tid + s]; __syncthreads(); }
        E = sred[0]; __syncthreads();

        if (tid == 0) {
            float px2 = px * px, py2 = py * py, pz2 = pz * pz;
            float pt = sqrtf(px2 + py2);
            float mass2 = E * E - px2 - py2 - pz2;
            float absp = sqrtf(px2 + py2 + pz2);
            float cosT = (absp == 0.f) ? 1.f : pz / absp;
            bool okc = cosT * cosT < 1.f;
            float ratio = okc ? (1.f - cosT) / (1.f + cosT) : 1.f;
            float eta = okc ? -0.5f * logf(ratio) : 0.f;
            float phi = (px == 0.f && py == 0.f) ? 0.f : atan2f(py, px);
            out[b * 6 + 0] = x20;
            out[b * 6 + 1] = x21;
            out[b * 6 + 2] = pt;
            out[b * 6 + 3] = eta;
            out[b * 6 + 4] = phi;
            out[b * 6 + 5] = mass2;
        }
    }
}

// ---------------- launcher: ONE node in the graph ----------------
extern "C" void kernel_launch(void* const* d_in, const int* in_sizes, int n_in,
                              void* d_out, int out_size)
{
    // dynamic smem: NBUF*(144*16 + 144*32) + 4096 + 128 + 16 ints
    const int smem_bytes = (NBUF * 144 * 16 + NBUF * 144 * 32 + 4096 + 128 + 16) * 4;
    static int attr_done = 0;
    if (!attr_done) {
        cudaFuncSetAttribute(mega_kernel,
                             cudaFuncAttributeMaxDynamicSharedMemorySize, smem_bytes);
        attr_done = 1;
    }
    mega_kernel<<<NB, NT, smem_bytes>>>(
        (const float*)d_in[0],  (const float*)d_in[1],  (const float*)d_in[2],
        (const float*)d_in[3],  (const float*)d_in[4],  (const float*)d_in[5],
        (const float*)d_in[6],  (const float*)d_in[7],  (const float*)d_in[8],
        (const float*)d_in[9],  (const float*)d_in[10], (const float*)d_in[11],
        (const float*)d_in[12], (const float*)d_in[13], (const float*)d_in[14],
        (const float*)d_in[15], (const float*)d_in[16], (const float*)d_in[17],
        (const float*)d_in[18], (const float*)d_in[19], (const float*)d_in[20],
        (const float*)d_in[21], (float*)d_out);
}